// round 7
// baseline (speedup 1.0000x reference)
#include <cuda_runtime.h>
#include <math.h>
#include <stdint.h>

#define MM 5000
#define EE 128
#define DD 512
#define DII 2048
#define CC 256
#define SS 32
#define BB 32
#define TT 64
#define TMS 63
#define LP 1954
#define LNN 2017
#define CSZ 8
#define RPC 2
#define NTH 256

#define DYN_FLOATS (1024*4 + 4096 + 8064*2 + 32 + 4 + LP + LNN + LP)
#define DYN_BYTES (DYN_FLOATS * 4)

__device__ int   g_cand[CC];
__device__ float g_At[EE * CC];
__device__ float g_Bm[MM * EE];
__device__ int   g_nlist[MM * SS];
__device__ float g_nprob[MM * SS];

__device__ __forceinline__ void tf2x32(uint32_t k0, uint32_t k1, uint32_t x0, uint32_t x1,
                                       uint32_t& o0, uint32_t& o1) {
    uint32_t k2 = k0 ^ k1 ^ 0x1BD11BDAu;
    x0 += k0; x1 += k1;
#define TF_R(r) { x0 += x1; x1 = (x1 << r) | (x1 >> (32 - r)); x1 ^= x0; }
    TF_R(13) TF_R(15) TF_R(26) TF_R(6)   x0 += k1; x1 += k2 + 1u;
    TF_R(17) TF_R(29) TF_R(16) TF_R(24)  x0 += k2; x1 += k0 + 2u;
    TF_R(13) TF_R(15) TF_R(26) TF_R(6)   x0 += k0; x1 += k1 + 3u;
    TF_R(17) TF_R(29) TF_R(16) TF_R(24)  x0 += k1; x1 += k2 + 4u;
    TF_R(13) TF_R(15) TF_R(26) TF_R(6)   x0 += k2; x1 += k0 + 5u;
#undef TF_R
    o0 = x0; o1 = x1;
}
__device__ __forceinline__ uint32_t rbits(uint32_t k0, uint32_t k1, uint32_t idx) {
    uint32_t a, b; tf2x32(k0, k1, 0u, idx, a, b); return a ^ b;
}
__device__ __forceinline__ float gumbel_u32(uint32_t bits) {
    const float tiny = 1.17549435e-38f;
    float f = __uint_as_float((bits >> 9) | 0x3f800000u) - 1.0f;
    float u = fmaxf(tiny, f + tiny);
    return -logf(-logf(u));
}

#define CLUSTER_SYNC() do { \
    asm volatile("barrier.cluster.arrive.aligned;" ::: "memory"); \
    asm volatile("barrier.cluster.wait.aligned;" ::: "memory"); } while (0)

__device__ __forceinline__ uint32_t smem_u32(const void* p) {
    uint32_t a;
    asm("{ .reg .u64 t; cvta.to.shared.u64 t, %1; cvt.u32.u64 %0, t; }" : "=r"(a) : "l"(p));
    return a;
}
__device__ __forceinline__ void dst_f(uint32_t la, int rk, float v) {
    uint32_t ra;
    asm volatile("mapa.shared::cluster.u32 %0, %1, %2;" : "=r"(ra) : "r"(la), "r"(rk));
    asm volatile("st.shared::cluster.f32 [%0], %1;" :: "r"(ra), "f"(v) : "memory");
}
__device__ __forceinline__ void dst_u(uint32_t la, int rk, uint32_t v) {
    uint32_t ra;
    asm volatile("mapa.shared::cluster.u32 %0, %1, %2;" : "=r"(ra) : "r"(la), "r"(rk));
    asm volatile("st.shared::cluster.u32 [%0], %1;" :: "r"(ra), "r"(v) : "memory");
}
__device__ __forceinline__ void bcast4(uint32_t la, float4 v) {
#pragma unroll
    for (int p = 0; p < CSZ; p++) {
        uint32_t ra;
        asm volatile("mapa.shared::cluster.u32 %0, %1, %2;" : "=r"(ra) : "r"(la), "r"(p));
        asm volatile("st.shared::cluster.v4.f32 [%0], {%1,%2,%3,%4};"
                     :: "r"(ra), "f"(v.x), "f"(v.y), "f"(v.z), "f"(v.w) : "memory");
    }
}

__device__ __forceinline__ float blockSum(float v, float* rs) {
    int tid = threadIdx.x, w = tid >> 5, l = tid & 31, nw = blockDim.x >> 5;
#pragma unroll
    for (int o = 16; o > 0; o >>= 1) v += __shfl_xor_sync(~0u, v, o);
    if (l == 0) rs[w] = v;
    __syncthreads();
    if (w == 0) {
        float x = (l < nw) ? rs[l] : 0.0f;
#pragma unroll
        for (int o = 16; o > 0; o >>= 1) x += __shfl_xor_sync(~0u, x, o);
        if (l == 0) rs[0] = x;
    }
    __syncthreads();
    float r = rs[0]; __syncthreads(); return r;
}
__device__ __forceinline__ float blockMax(float v, float* rs) {
    int tid = threadIdx.x, w = tid >> 5, l = tid & 31, nw = blockDim.x >> 5;
#pragma unroll
    for (int o = 16; o > 0; o >>= 1) v = fmaxf(v, __shfl_xor_sync(~0u, v, o));
    if (l == 0) rs[w] = v;
    __syncthreads();
    if (w == 0) {
        float x = (l < nw) ? rs[l] : -INFINITY;
#pragma unroll
        for (int o = 16; o > 0; o >>= 1) x = fmaxf(x, __shfl_xor_sync(~0u, x, o));
        if (l == 0) rs[0] = x;
    }
    __syncthreads();
    float r = rs[0]; __syncthreads(); return r;
}
__device__ __forceinline__ void warpArgmax(float& v, int& idx) {
#pragma unroll
    for (int o = 16; o > 0; o >>= 1) {
        float ov = __shfl_xor_sync(~0u, v, o);
        int   oi = __shfl_xor_sync(~0u, idx, o);
        if (ov > v || (ov == v && oi < idx)) { v = ov; idx = oi; }
    }
}
__device__ __forceinline__ void blockArgmax(float& v, int& idx, float* rv, int* ri) {
    int tid = threadIdx.x, w = tid >> 5, l = tid & 31, nw = (blockDim.x + 31) >> 5;
    warpArgmax(v, idx);
    if (l == 0) { rv[w] = v; ri[w] = idx; }
    __syncthreads();
    if (w == 0) {
        float vv = (l < nw) ? rv[l] : -INFINITY;
        int   ii = (l < nw) ? ri[l] : 0x7fffffff;
        warpArgmax(vv, ii);
        if (l == 0) { rv[0] = vv; ri[0] = ii; }
    }
    __syncthreads();
    v = rv[0]; idx = ri[0]; __syncthreads();
}

__global__ void __launch_bounds__(1024) k_topk_cand() {
    __shared__ float vals[MM];
    __shared__ float rv[32]; __shared__ int ri[32];
    uint32_t ka, kb; tf2x32(0u, 7u, 0u, 0u, ka, kb);
    for (int i = threadIdx.x; i < MM; i += blockDim.x)
        vals[i] = gumbel_u32(rbits(ka, kb, (uint32_t)i));
    __syncthreads();
    for (int r = 0; r < CC; r++) {
        float bv = -INFINITY; int bi = 0x7fffffff;
        for (int i = threadIdx.x; i < MM; i += blockDim.x) {
            float v = vals[i];
            if (v > bv) { bv = v; bi = i; }
        }
        blockArgmax(bv, bi, rv, ri);
        if (threadIdx.x == 0) { g_cand[r] = bi; vals[bi] = -INFINITY; }
        __syncthreads();
    }
}

__global__ void __launch_bounds__(EE) k_bm(const float* __restrict__ emb,
                                           const float* __restrict__ s1w) {
    __shared__ float se[EE];
    int m = blockIdx.x, d = threadIdx.x;
    se[d] = emb[m * EE + d];
    __syncthreads();
    float acc = 0.0f;
#pragma unroll 8
    for (int e = 0; e < EE; e++) acc += se[e] * s1w[(EE + e) * EE + d];
    g_Bm[m * EE + d] = acc;
}

__global__ void __launch_bounds__(EE) k_a(const float* __restrict__ emb,
                                          const float* __restrict__ s1w) {
    __shared__ float se[EE];
    int c = blockIdx.x, d = threadIdx.x;
    se[d] = emb[g_cand[c] * EE + d];
    __syncthreads();
    float acc = 0.0f;
#pragma unroll 8
    for (int e = 0; e < EE; e++) acc += se[e] * s1w[e * EE + d];
    g_At[d * CC + c] = acc;
}

__global__ void __launch_bounds__(CC) k_select(const float* __restrict__ s1b,
                                               const float* __restrict__ s2w,
                                               const float* __restrict__ s2b) {
    __shared__ float sb[EE], sw[EE], sbm[EE];
    __shared__ float p[CC], sc[CC];
    __shared__ float rs[32], rv[32]; __shared__ int ri[32];
    int m = blockIdx.x, c = threadIdx.x;
    if (c < EE) { sb[c] = s1b[c]; sw[c] = s2w[c]; sbm[c] = g_Bm[m * EE + c]; }
    __syncthreads();
    float acc = 0.0f;
#pragma unroll 4
    for (int e = 0; e < EE; e++) {
        float t = g_At[e * CC + c] + sbm[e] + sb[e];
        t = (t >= 0.0f) ? t : 0.01f * t;
        acc += t * sw[e];
    }
    float logit = acc + s2b[0];
    float mx = blockMax(logit, rs);
    float ex = expf(logit - mx);
    float sm = blockSum(ex, rs);
    float pc = ex / sm;
    p[c] = pc;
    uint32_t ka, kb; tf2x32(0u, 7u, 0u, 1u, ka, kb);
    sc[c] = logf(pc) + gumbel_u32(rbits(ka, kb, (uint32_t)(m * CC + c)));
    __syncthreads();
    for (int s = 0; s < SS; s++) {
        float bv = sc[c]; int bi = c;
        blockArgmax(bv, bi, rv, ri);
        if (threadIdx.x == 0) {
            g_nlist[m * SS + s] = g_cand[bi];
            g_nprob[m * SS + s] = p[bi];
            sc[bi] = -INFINITY;
        }
        __syncthreads();
    }
}

#define GEMM2(W, LDN, COL0, X0, X1, NC, K)                                   \
  {                                                                          \
    const int G_ = (NC) / 4, P_ = NTH / G_, KC_ = (K) / P_;                  \
    const int g_ = tid % G_, p_ = tid / G_;                                  \
    const float4* Wb_ = (const float4*)(W) + ((COL0) >> 2) + g_;             \
    const int ld4_ = (LDN) >> 2;                                             \
    float4 a0_ = make_float4(0.f,0.f,0.f,0.f), a1_ = a0_;                    \
    int k_ = p_ * KC_;                                                       \
    _Pragma("unroll 8")                                                      \
    for (int kk_ = 0; kk_ < KC_; kk_++, k_++) {                              \
      float4 w4_ = Wb_[(size_t)k_ * ld4_];                                   \
      float xa_ = (X0)[k_], xb_ = (X1)[k_];                                  \
      a0_.x += xa_*w4_.x; a0_.y += xa_*w4_.y; a0_.z += xa_*w4_.z; a0_.w += xa_*w4_.w; \
      a1_.x += xb_*w4_.x; a1_.y += xb_*w4_.y; a1_.z += xb_*w4_.z; a1_.w += xb_*w4_.w; \
    }                                                                        \
    s_scr[p_ * G_ + g_] = a0_;                                               \
    s_scr[256 + p_ * G_ + g_] = a1_;                                         \
    __syncthreads();                                                         \
  }

__device__ __forceinline__ float4 redP(const float4* scr, int r, int g, int G, int P) {
    float4 a = scr[r * 256 + g];
    for (int p = 1; p < P; p++) {
        float4 b = scr[r * 256 + p * G + g];
        a.x += b.x; a.y += b.y; a.z += b.z; a.w += b.w;
    }
    return a;
}

__global__ void __launch_bounds__(NTH) __cluster_dims__(CSZ, 1, 1) k_seq_cl(
    const int* __restrict__ marker_data, const float* __restrict__ time_data,
    const float* __restrict__ mask_data, const float* __restrict__ emb,
    const float* __restrict__ te_w, const float* __restrict__ te_b,
    const float* __restrict__ el_w, const float* __restrict__ el_b,
    const float* __restrict__ ml_w, const float* __restrict__ ml_b,
    const float* __restrict__ tl_w, const float* __restrict__ tl_b,
    const float* __restrict__ wq, const float* __restrict__ wk,
    const float* __restrict__ wv, const float* __restrict__ wo,
    const float* __restrict__ wo_b,
    const float* __restrict__ ln1_s, const float* __restrict__ ln1_b,
    const float* __restrict__ ff1_w, const float* __restrict__ ff1_b,
    const float* __restrict__ ff2_w, const float* __restrict__ ff2_b,
    const float* __restrict__ ln2_s, const float* __restrict__ ln2_b,
    float* __restrict__ out)
{
    const int tid = threadIdx.x;
    const int rank = blockIdx.x & (CSZ - 1);
    const int cid = blockIdx.x / CSZ;
    const int R0 = cid * RPC, R1 = R0 + 1;
    const int col64 = rank * 64, col256 = rank * 256;

    extern __shared__ float smb[];
    float* s_md  = smb;
    float* s_x1  = s_md + 1024;
    float* s_int = s_x1 + 1024;
    float* s_ctx = s_int + 1024;
    float* s_h1  = s_ctx + 1024;
    float* s_kc  = s_h1 + 4096;
    float* s_vc  = s_kc + 8064;
    float* s_lnp = s_vc + 8064;
    int*   s_lm  = (int*)(s_lnp + 32);
    float* s_lt  = (float*)(s_lm + 2);
    float* s_prob = s_lt + 2;
    float* s_nrec = s_prob + LP;
    int*   s_cand = (int*)(s_nrec + LNN);

    __shared__ float4 s_scr[512];
    __shared__ float  s_vv[256], s_qh[128], s_sct[128], s_mw[SS];
    __shared__ int    s_nb[SS];
    __shared__ float  rs[32], rv[32];
    __shared__ int    ri[32];
    __shared__ int    s_chosen[2];

    const uint32_t u_md  = smem_u32(s_md);
    const uint32_t u_x1  = smem_u32(s_x1);
    const uint32_t u_int = smem_u32(s_int);
    const uint32_t u_ctx = smem_u32(s_ctx);
    const uint32_t u_h1  = smem_u32(s_h1);
    const uint32_t u_lnp = smem_u32(s_lnp);
    const uint32_t u_lm  = smem_u32(s_lm);
    const uint32_t u_lt  = smem_u32(s_lt);

    if (tid == 0) {
        s_lm[0] = marker_data[R0 * TT]; s_lm[1] = marker_data[R1 * TT];
        s_lt[0] = time_data[R0 * TT];   s_lt[1] = time_data[R1 * TT];
        s_chosen[0] = 0; s_chosen[1] = 0;
    }
    if (rank < RPC) {
        const int R = (rank == 0) ? R0 : R1;
        for (int j = tid; j < LP;  j += NTH) { s_prob[j] = 0.0f; s_cand[j] = 0; }
        for (int j = tid; j < LNN; j += NTH) s_nrec[j] = 0.0f;
        if (tid == 0) {
            int m0 = marker_data[R * TT]; float t0 = time_data[R * TT];
            s_prob[0] = 1.0f; s_cand[0] = m0; s_nrec[0] = 1.0f;
            out[0*(BB*TT) + R*TT] = (float)m0;
            out[1*(BB*TT) + R*TT] = t0;
            out[2*(BB*TT) + R*TT] = mask_data[R*TT];
            out[3*(BB*TT) + R*TT] = 1.0f;
            out[4*(BB*TT) + R*TT] = 1.0f;
        }
    }
    __syncthreads();
    CLUSTER_SYNC();

    for (int i = 0; i < TMS; i++) {
        const int lm0 = s_lm[0], lm1 = s_lm[1];
        const float lt0 = s_lt[0], lt1 = s_lt[1];

        {
            int r = tid >> 7, e = tid & 127;
            int lmr = r ? lm1 : lm0; float ltr = r ? lt1 : lt0;
            s_vv[tid] = emb[lmr * EE + e] + 0.1f * (ltr * te_w[e] + te_b[e]);
        }
        __syncthreads();

        GEMM2(el_w, DD, col64, s_vv, s_vv + 128, 64, 128)
        if (tid < 32) {
            int r = tid >> 4, g = tid & 15;
            float4 a = redP(s_scr, r, g, 16, 16);
            float4 bq = ((const float4*)el_b)[(col64 >> 2) + g];
            a.x += bq.x; a.y += bq.y; a.z += bq.z; a.w += bq.w;
            a.x = (a.x >= 0.f) ? a.x : 0.01f * a.x;
            a.y = (a.y >= 0.f) ? a.y : 0.01f * a.y;
            a.z = (a.z >= 0.f) ? a.z : 0.01f * a.z;
            a.w = (a.w >= 0.f) ? a.w : 0.01f * a.w;
            bcast4(u_md + (uint32_t)(r * 512 + col64 + g * 4) * 4u, a);
        }
        CLUSTER_SYNC();

        GEMM2(wq, DD, col64, s_md, s_md + 512, 64, 512)
        if (tid < 32) {
            int r = tid >> 4, g = tid & 15;
            ((float4*)s_qh)[r * 16 + g] = redP(s_scr, r, g, 16, 16);
        }
        __syncthreads();
        GEMM2(wk, DD, col64, s_md, s_md + 512, 64, 512)
        if (tid < 32) {
            int r = tid >> 4, g = tid & 15;
            ((float4*)s_kc)[(r * TMS + i) * 16 + g] = redP(s_scr, r, g, 16, 16);
        }
        __syncthreads();
        GEMM2(wv, DD, col64, s_md, s_md + 512, 64, 512)
        if (tid < 32) {
            int r = tid >> 4, g = tid & 15;
            ((float4*)s_vc)[(r * TMS + i) * 16 + g] = redP(s_scr, r, g, 16, 16);
        }
        __syncthreads();

        if (tid < 2 * (i + 1)) {
            int r = tid & 1, t = tid >> 1;
            const float4* kp = (const float4*)&s_kc[(r * TMS + t) * 64];
            const float4* qp = (const float4*)&s_qh[r * 64];
            float acc = 0.0f;
#pragma unroll
            for (int d = 0; d < 16; d++) {
                float4 q4 = qp[d], k4 = kp[d];
                acc += q4.x*k4.x + q4.y*k4.y + q4.z*k4.z + q4.w*k4.w;
            }
            s_sct[r * 64 + t] = acc * 0.125f;
        }
        __syncthreads();
        if (tid < 2) {
            int r = tid;
            float mx = -INFINITY;
            for (int t = 0; t <= i; t++) mx = fmaxf(mx, s_sct[r * 64 + t]);
            float sm = 0.0f;
            for (int t = 0; t <= i; t++) {
                float e = expf(s_sct[r * 64 + t] - mx);
                s_sct[r * 64 + t] = e; sm += e;
            }
            for (int t = 0; t <= i; t++) s_sct[r * 64 + t] /= sm;
        }
        __syncthreads();
        if (tid < 32) {
            int r = tid >> 4, g = tid & 15;
            float4 acc = make_float4(0.f, 0.f, 0.f, 0.f);
            for (int t = 0; t <= i; t++) {
                float pp = s_sct[r * 64 + t];
                float4 v4 = ((const float4*)s_vc)[(r * TMS + t) * 16 + g];
                acc.x += pp*v4.x; acc.y += pp*v4.y; acc.z += pp*v4.z; acc.w += pp*v4.w;
            }
            bcast4(u_ctx + (uint32_t)(r * 512 + col64 + g * 4) * 4u, acc);
        }
        CLUSTER_SYNC();

        GEMM2(wo, DD, col64, s_ctx, s_ctx + 512, 64, 512)
        if (tid < 32) {
            int r = tid >> 4, g = tid & 15;
            float4 a = redP(s_scr, r, g, 16, 16);
            float4 bq = ((const float4*)wo_b)[(col64 >> 2) + g];
            float4 m4 = ((const float4*)s_md)[r * 128 + (col64 >> 2) + g];
            float4 val;
            val.x = m4.x + a.x + bq.x; val.y = m4.y + a.y + bq.y;
            val.z = m4.z + a.z + bq.z; val.w = m4.w + a.w + bq.w;
            bcast4(u_x1 + (uint32_t)(r * 512 + col64 + g * 4) * 4u, val);
            float s1 = val.x + val.y + val.z + val.w;
            float s2 = val.x*val.x + val.y*val.y + val.z*val.z + val.w*val.w;
#pragma unroll
            for (int o = 1; o < 16; o <<= 1) {
                s1 += __shfl_xor_sync(~0u, s1, o);
                s2 += __shfl_xor_sync(~0u, s2, o);
            }
            if ((tid & 15) == 0) {
                uint32_t la = u_lnp + (uint32_t)((r * 8 + rank) * 2) * 4u;
#pragma unroll
                for (int p = 0; p < CSZ; p++) { dst_f(la, p, s1); dst_f(la + 4, p, s2); }
            }
        }
        CLUSTER_SYNC();
        {
            float m0 = 0.f, q0 = 0.f, m1 = 0.f, q1 = 0.f;
#pragma unroll
            for (int j = 0; j < 8; j++) {
                m0 += s_lnp[j*2]; q0 += s_lnp[j*2+1];
                m1 += s_lnp[16+j*2]; q1 += s_lnp[16+j*2+1];
            }
            m0 /= (float)DD; m1 /= (float)DD;
            float dn0 = sqrtf(fmaxf(q0/(float)DD - m0*m0, 0.f) + 1e-5f);
            float dn1 = sqrtf(fmaxf(q1/(float)DD - m1*m1, 0.f) + 1e-5f);
            for (int idx = tid; idx < 1024; idx += NTH) {
                int r = idx >> 9, c = idx & 511;
                float mean = r ? m1 : m0, dn = r ? dn1 : dn0;
                s_x1[idx] = (s_x1[idx] - mean) / dn * ln1_s[c] + ln1_b[c];
            }
        }
        __syncthreads();

        GEMM2(ff1_w, DII, col256, s_x1, s_x1 + 512, 256, 512)
        if (tid < 128) {
            int r = tid >> 6, g = tid & 63;
            float4 a = redP(s_scr, r, g, 64, 4);
            float4 bq = ((const float4*)ff1_b)[(col256 >> 2) + g];
            a.x = fmaxf(a.x + bq.x, 0.f); a.y = fmaxf(a.y + bq.y, 0.f);
            a.z = fmaxf(a.z + bq.z, 0.f); a.w = fmaxf(a.w + bq.w, 0.f);
            bcast4(u_h1 + (uint32_t)(r * 2048 + col256 + g * 4) * 4u, a);
        }
        CLUSTER_SYNC();

        GEMM2(ff2_w, DD, col64, s_h1, s_h1 + 2048, 64, 2048)
        if (tid < 32) {
            int r = tid >> 4, g = tid & 15;
            float4 a = redP(s_scr, r, g, 16, 16);
            float4 bq = ((const float4*)ff2_b)[(col64 >> 2) + g];
            float4 x4 = ((const float4*)s_x1)[r * 128 + (col64 >> 2) + g];
            float4 val;
            val.x = x4.x + a.x + bq.x; val.y = x4.y + a.y + bq.y;
            val.z = x4.z + a.z + bq.z; val.w = x4.w + a.w + bq.w;
            bcast4(u_int + (uint32_t)(r * 512 + col64 + g * 4) * 4u, val);
            float s1 = val.x + val.y + val.z + val.w;
            float s2 = val.x*val.x + val.y*val.y + val.z*val.z + val.w*val.w;
#pragma unroll
            for (int o = 1; o < 16; o <<= 1) {
                s1 += __shfl_xor_sync(~0u, s1, o);
                s2 += __shfl_xor_sync(~0u, s2, o);
            }
            if ((tid & 15) == 0) {
                uint32_t la = u_lnp + (uint32_t)((r * 8 + rank) * 2) * 4u;
#pragma unroll
                for (int p = 0; p < CSZ; p++) { dst_f(la, p, s1); dst_f(la + 4, p, s2); }
            }
        }
        CLUSTER_SYNC();
        {
            float m0 = 0.f, q0 = 0.f, m1 = 0.f, q1 = 0.f;
#pragma unroll
            for (int j = 0; j < 8; j++) {
                m0 += s_lnp[j*2]; q0 += s_lnp[j*2+1];
                m1 += s_lnp[16+j*2]; q1 += s_lnp[16+j*2+1];
            }
            m0 /= (float)DD; m1 /= (float)DD;
            float dn0 = sqrtf(fmaxf(q0/(float)DD - m0*m0, 0.f) + 1e-5f);
            float dn1 = sqrtf(fmaxf(q1/(float)DD - m1*m1, 0.f) + 1e-5f);
            for (int idx = tid; idx < 1024; idx += NTH) {
                int r = idx >> 9, c = idx & 511;
                float mean = r ? m1 : m0, dn = r ? dn1 : dn0;
                s_int[idx] = (s_int[idx] - mean) / dn * ln2_s[c] + ln2_b[c];
            }
        }
        __syncthreads();

        if (rank < RPC) {
            const int r = rank;
            const int R = r ? R1 : R0;
            const int lm = r ? lm1 : lm0;
            const float lt = r ? lt1 : lt0;
            const int chosen = s_chosen[r];
            const float* iv = s_int + r * 512;

            float tv = 0.f, mv = 0.f;
            for (int e = tid; e < DD; e += NTH) {
                tv += iv[e] * tl_w[e];
                mv += iv[e] * ml_w[EE + e];
            }
            float tdot = blockSum(tv, rs) + tl_b[0];
            float iml = blockSum(mv, rs);
            float nt = lt + (fmaxf(tdot, 0.f) + log1pf(expf(-fabsf(tdot))));

            if (tid < SS) {
                s_nb[tid] = g_nlist[lm * SS + tid];
                s_nrec[1 + i * SS + tid] = g_nprob[lm * SS + tid];
            }
            __syncthreads();
            if (tid < SS) {
                float acc = 0.0f;
                const float4* ep = (const float4*)&emb[s_nb[tid] * EE];
                const float4* mw4 = (const float4*)ml_w;
#pragma unroll
                for (int e = 0; e < 32; e++) {
                    float4 a4 = ep[e], w4 = mw4[e];
                    acc += a4.x*w4.x + a4.y*w4.y + a4.z*w4.z + a4.w*w4.w;
                }
                s_mw[tid] = acc + iml + ml_b[0];
            }
            __syncthreads();
            if (tid < SS) {
                float v = s_mw[tid];
                float mx = v;
#pragma unroll
                for (int o = 16; o > 0; o >>= 1) mx = fmaxf(mx, __shfl_xor_sync(~0u, mx, o));
                float ex = expf(v - mx);
                float sm = ex;
#pragma unroll
                for (int o = 16; o > 0; o >>= 1) sm += __shfl_xor_sync(~0u, sm, o);
                float mp = ex / sm;
                float pc = s_prob[chosen];
                __syncwarp();
                float att = pc * mp;
                if (tid == 0) s_prob[chosen] = att;
                else {
                    s_prob[1 + i * (SS - 1) + tid - 1] = att;
                    s_cand[1 + i * (SS - 1) + tid - 1] = s_nb[tid];
                }
            }
            __syncthreads();

            uint32_t ka, kb;
            tf2x32(0u, 11u, 0u, (uint32_t)i, ka, kb);
            float bv = -INFINITY; int bi = 0x7fffffff;
            for (int j = tid; j < LP; j += NTH) {
                float z = logf(s_prob[j]) + gumbel_u32(rbits(ka, kb, (uint32_t)(R * LP + j)));
                if (z > bv) { bv = z; bi = j; }
            }
            blockArgmax(bv, bi, rv, ri);

            if (tid == 0) {
                int nc = bi, nm = s_cand[nc];
                s_chosen[r] = nc;
                int o = R * TT + (i + 1);
                out[0*(BB*TT) + o] = (float)nm;
                out[1*(BB*TT) + o] = nt;
                out[2*(BB*TT) + o] = (nt < 50.0f) ? 1.0f : 0.0f;
                out[3*(BB*TT) + o] = s_nrec[nc];
                out[4*(BB*TT) + o] = s_prob[nc];
#pragma unroll
                for (int p = 0; p < CSZ; p++) {
                    dst_u(u_lm + (uint32_t)r * 4u, p, (uint32_t)nm);
                    dst_f(u_lt + (uint32_t)r * 4u, p, nt);
                }
            }
        }
        CLUSTER_SYNC();
    }
}

extern "C" void kernel_launch(void* const* d_in, const int* in_sizes, int n_in,
                              void* d_out, int out_size) {
    const int*   marker = (const int*)  d_in[0];
    const float* timed  = (const float*)d_in[1];
    const float* maskd  = (const float*)d_in[2];
    const float* emb    = (const float*)d_in[3];
    const float* te_w   = (const float*)d_in[4];
    const float* te_b   = (const float*)d_in[5];
    const float* el_w   = (const float*)d_in[6];
    const float* el_b   = (const float*)d_in[7];
    const float* s1_w   = (const float*)d_in[8];
    const float* s1_b   = (const float*)d_in[9];
    const float* s2_w   = (const float*)d_in[10];
    const float* s2_b   = (const float*)d_in[11];
    const float* ml_w   = (const float*)d_in[12];
    const float* ml_b   = (const float*)d_in[13];
    const float* tl_w   = (const float*)d_in[14];
    const float* tl_b   = (const float*)d_in[15];
    const float* wq     = (const float*)d_in[16];
    const float* wk     = (const float*)d_in[17];
    const float* wv     = (const float*)d_in[18];
    const float* wo     = (const float*)d_in[19];
    const float* wo_b   = (const float*)d_in[20];
    const float* ln1_s  = (const float*)d_in[21];
    const float* ln1_b  = (const float*)d_in[22];
    const float* ff1_w  = (const float*)d_in[23];
    const float* ff1_b  = (const float*)d_in[24];
    const float* ff2_w  = (const float*)d_in[25];
    const float* ff2_b  = (const float*)d_in[26];
    const float* ln2_s  = (const float*)d_in[27];
    const float* ln2_b  = (const float*)d_in[28];
    float* out = (float*)d_out;

    static int inited = 0;
    if (!inited) {
        cudaFuncSetAttribute(k_seq_cl, cudaFuncAttributeMaxDynamicSharedMemorySize,
                             DYN_BYTES);
        cudaFuncSetAttribute(k_seq_cl, cudaFuncAttributeNonPortableClusterSizeAllowed, 1);
        inited = 1;
    }

    k_topk_cand<<<1, 1024>>>();
    k_bm<<<MM, EE>>>(emb, s1_w);
    k_a<<<CC, EE>>>(emb, s1_w);
    k_select<<<MM, CC>>>(s1_b, s2_w, s2_b);
    k_seq_cl<<<(BB / RPC) * CSZ, NTH, DYN_BYTES>>>(
        marker, timed, maskd, emb, te_w, te_b, el_w, el_b, ml_w, ml_b,
        tl_w, tl_b, wq, wk, wv, wo, wo_b, ln1_s, ln1_b,
        ff1_w, ff1_b, ff2_w, ff2_b, ln2_s, ln2_b, out);
}